// round 1
// baseline (speedup 1.0000x reference)
#include <cuda_runtime.h>
#include <cuda_bf16.h>

#define NG 128
#define NT 512
#define SDIM 24
#define MDIM 4
#define SP 28          // padded row stride (floats), 16B-aligned rows
#define NTHREADS 576

// Classic 4x4 inverse via cofactors (matrix is SPD -> well conditioned).
__device__ __forceinline__ void inv4x4(const float* m, float* invOut) {
    float inv[16];
    inv[0]  =  m[5]*m[10]*m[15] - m[5]*m[11]*m[14] - m[9]*m[6]*m[15] + m[9]*m[7]*m[14] + m[13]*m[6]*m[11] - m[13]*m[7]*m[10];
    inv[4]  = -m[4]*m[10]*m[15] + m[4]*m[11]*m[14] + m[8]*m[6]*m[15] - m[8]*m[7]*m[14] - m[12]*m[6]*m[11] + m[12]*m[7]*m[10];
    inv[8]  =  m[4]*m[9]*m[15]  - m[4]*m[11]*m[13] - m[8]*m[5]*m[15] + m[8]*m[7]*m[13] + m[12]*m[5]*m[11] - m[12]*m[7]*m[9];
    inv[12] = -m[4]*m[9]*m[14]  + m[4]*m[10]*m[13] + m[8]*m[5]*m[14] - m[8]*m[6]*m[13] - m[12]*m[5]*m[10] + m[12]*m[6]*m[9];
    inv[1]  = -m[1]*m[10]*m[15] + m[1]*m[11]*m[14] + m[9]*m[2]*m[15] - m[9]*m[3]*m[14] - m[13]*m[2]*m[11] + m[13]*m[3]*m[10];
    inv[5]  =  m[0]*m[10]*m[15] - m[0]*m[11]*m[14] - m[8]*m[2]*m[15] + m[8]*m[3]*m[14] + m[12]*m[2]*m[11] - m[12]*m[3]*m[10];
    inv[9]  = -m[0]*m[9]*m[15]  + m[0]*m[11]*m[13] + m[8]*m[1]*m[15] - m[8]*m[3]*m[13] - m[12]*m[1]*m[11] + m[12]*m[3]*m[9];
    inv[13] =  m[0]*m[9]*m[14]  - m[0]*m[10]*m[13] - m[8]*m[1]*m[14] + m[8]*m[2]*m[13] + m[12]*m[1]*m[10] - m[12]*m[2]*m[9];
    inv[2]  =  m[1]*m[6]*m[15]  - m[1]*m[7]*m[14]  - m[5]*m[2]*m[15] + m[5]*m[3]*m[14] + m[13]*m[2]*m[7]  - m[13]*m[3]*m[6];
    inv[6]  = -m[0]*m[6]*m[15]  + m[0]*m[7]*m[14]  + m[4]*m[2]*m[15] - m[4]*m[3]*m[14] - m[12]*m[2]*m[7]  + m[12]*m[3]*m[6];
    inv[10] =  m[0]*m[5]*m[15]  - m[0]*m[7]*m[13]  - m[4]*m[1]*m[15] + m[4]*m[3]*m[13] + m[12]*m[1]*m[7]  - m[12]*m[3]*m[5];
    inv[14] = -m[0]*m[5]*m[14]  + m[0]*m[6]*m[13]  + m[4]*m[1]*m[14] - m[4]*m[2]*m[13] - m[12]*m[1]*m[6]  + m[12]*m[2]*m[5];
    inv[3]  = -m[1]*m[6]*m[11]  + m[1]*m[7]*m[10]  + m[5]*m[2]*m[11] - m[5]*m[3]*m[10] - m[9]*m[2]*m[7]   + m[9]*m[3]*m[6];
    inv[7]  =  m[0]*m[6]*m[11]  - m[0]*m[7]*m[10]  - m[4]*m[2]*m[11] + m[4]*m[3]*m[10] + m[8]*m[2]*m[7]   - m[8]*m[3]*m[6];
    inv[11] = -m[0]*m[5]*m[11]  + m[0]*m[7]*m[9]   + m[4]*m[1]*m[11] - m[4]*m[3]*m[9]  - m[8]*m[1]*m[7]   + m[8]*m[3]*m[5];
    inv[15] =  m[0]*m[5]*m[10]  - m[0]*m[6]*m[9]   - m[4]*m[1]*m[10] + m[4]*m[2]*m[9]  + m[8]*m[1]*m[6]   - m[8]*m[2]*m[5];
    float det = m[0]*inv[0] + m[1]*inv[4] + m[2]*inv[8] + m[3]*inv[12];
    det = 1.0f / det;
    #pragma unroll
    for (int i = 0; i < 16; i++) invOut[i] = inv[i] * det;
}

__device__ __forceinline__ float dot24(const float4* a, const float4* b) {
    float acc = 0.f;
    #pragma unroll
    for (int c = 0; c < 6; ++c) {
        float4 x = a[c], y = b[c];
        acc += x.x*y.x + x.y*y.y + x.z*y.z + x.w*y.w;
    }
    return acc;
}

__global__ __launch_bounds__(NTHREADS, 1)
void kalman_kernel(const float* __restrict__ y_in,   // (G,T,M)
                   const float* __restrict__ F_in,   // (G,T,S,S)
                   const float* __restrict__ Q_in,   // (G,T,S,S)
                   const float* __restrict__ H_in,   // (G,T,M,S)
                   const float* __restrict__ R_in,   // (G,T,M,M)
                   const float* __restrict__ m0_in,  // (G,S)
                   const float* __restrict__ P0_in,  // (G,S,S)
                   float* __restrict__ out)
{
    __shared__ __align__(16) float P [SDIM*SP];
    __shared__ __align__(16) float W [SDIM*SP];
    __shared__ __align__(16) float Fs[2][SDIM*SP];
    __shared__ __align__(16) float Qs[2][SDIM*SP];
    __shared__ __align__(16) float Hs[2][MDIM*SP];
    __shared__ __align__(16) float HP[MDIM*SP];
    __shared__ float Rs[2][16];
    __shared__ float ys[2][4];
    __shared__ float Kk[SDIM*4];
    __shared__ float Sg[16];
    __shared__ float Sinv[16];
    __shared__ float mvec[SDIM];
    __shared__ float m_u[SDIM];
    __shared__ float mu_s[MDIM];
    __shared__ float resid[MDIM];

    const int g   = blockIdx.x;
    const int tid = threadIdx.x;
    const int w   = tid >> 5;
    const int l   = tid & 31;
    // warp-tiled (8 rows x 4 cols per warp) mapping for the 24x24 stages:
    const int ti  = (w % 3) * 8 + (l & 7);
    const int tj  = (w / 3) * 4 + (l >> 3);
    // linear mapping for coalesced global loads:
    const int li  = tid / 24;
    const int lj  = tid % 24;

    const size_t baseT = (size_t)g * NT;
    float* outMean = out;
    float* outCov  = out + (size_t)NG * NT * MDIM;

    // ---- prologue: init state + load t=0 buffers ----
    P[li*SP + lj] = P0_in[(size_t)g*SDIM*SDIM + tid];
    if (tid < SDIM) mvec[tid] = m0_in[g*SDIM + tid];
    Fs[0][li*SP + lj] = F_in[baseT*(SDIM*SDIM) + tid];
    Qs[0][li*SP + lj] = Q_in[baseT*(SDIM*SDIM) + tid];
    if (tid < 96)                    Hs[0][(tid/24)*SP + (tid%24)] = H_in[baseT*(MDIM*SDIM) + tid];
    else if (tid < 112)              Rs[0][tid-96]  = R_in[baseT*(MDIM*MDIM) + (tid-96)];
    else if (tid < 116)              ys[0][tid-112] = y_in[baseT*MDIM + (tid-112)];
    __syncthreads();

    for (int t = 0; t < NT; ++t) {
        const int cur = t & 1;
        const int nxt = cur ^ 1;

        // ---- prefetch next step into registers (latency hidden by the step) ----
        float fN = 0.f, qN = 0.f, hN = 0.f, rN = 0.f, yN = 0.f;
        if (t + 1 < NT) {
            size_t b = baseT + t + 1;
            fN = F_in[b*(SDIM*SDIM) + tid];
            qN = Q_in[b*(SDIM*SDIM) + tid];
            if (tid < 96)       hN = H_in[b*(MDIM*SDIM) + tid];
            else if (tid < 112) rN = R_in[b*(MDIM*MDIM) + (tid-96)];
            else if (tid < 116) yN = y_in[b*MDIM + (tid-112)];
        }

        // ---- S1: HP = H @ P (via P symmetry: row.row), mu = H @ m ----
        if (tid < 96) {
            int q = tid / 24, s = tid % 24;
            HP[q*SP + s] = dot24((const float4*)&Hs[cur][q*SP], (const float4*)&P[s*SP]);
        } else if (tid < 100) {
            int q = tid - 96;
            const float* hr = &Hs[cur][q*SP];
            float acc = 0.f;
            #pragma unroll
            for (int k = 0; k < SDIM; ++k) acc += hr[k]*mvec[k];
            mu_s[q] = acc;
            outMean[(baseT + t)*MDIM + q] = acc;    // emitted mean
        }
        __syncthreads();

        // ---- S2: Sig = HP @ H^T + R  (this IS both the output cov and Sm) ----
        if (tid < 16) {
            int q = tid >> 2, r = tid & 3;
            float acc = Rs[cur][tid] +
                        dot24((const float4*)&HP[q*SP], (const float4*)&Hs[cur][r*SP]);
            Sg[tid] = acc;
            outCov[(baseT + t)*16 + tid] = acc;     // emitted covariance
        } else if (tid < 20) {
            int q = tid - 16;
            resid[q] = ys[cur][q] - mu_s[q];
        }
        if (t == NT - 1) break;                     // uniform across block
        __syncthreads();

        // ---- S3: Sm^{-1} (4x4 cofactor inverse, one thread) ----
        if (tid == 0) inv4x4(Sg, Sinv);
        __syncthreads();

        // ---- S4: K[s][q] = sum_r Sinv[q][r] * HP[r][s] ----
        if (tid < 96) {
            int s = tid % 24, q = tid / 24;
            float acc = 0.f;
            #pragma unroll
            for (int r = 0; r < 4; ++r) acc += Sinv[q*4+r] * HP[r*SP + s];
            Kk[s*4 + q] = acc;
        }
        __syncthreads();

        // ---- S5: P <- P - K @ HP (in place);  m_u = m + K @ resid ----
        {
            float v = P[ti*SP + tj];
            v -= Kk[ti*4+0]*HP[0*SP+tj] + Kk[ti*4+1]*HP[1*SP+tj]
               + Kk[ti*4+2]*HP[2*SP+tj] + Kk[ti*4+3]*HP[3*SP+tj];
            P[ti*SP + tj] = v;
        }
        if (tid < SDIM) {
            float acc = mvec[tid];
            #pragma unroll
            for (int q = 0; q < 4; ++q) acc += Kk[tid*4+q]*resid[q];
            m_u[tid] = acc;
        }
        __syncthreads();

        // ---- S6: W = F @ P_u (P_u symmetric -> row.row);  m <- F @ m_u ----
        W[ti*SP + tj] = dot24((const float4*)&Fs[cur][ti*SP], (const float4*)&P[tj*SP]);
        if (tid < SDIM) {
            const float* fr = &Fs[cur][tid*SP];
            float acc = 0.f;
            #pragma unroll
            for (int k = 0; k < SDIM; ++k) acc += fr[k]*m_u[k];
            mvec[tid] = acc;
        }
        __syncthreads();

        // ---- S7: P = W @ F^T + Q;  stash prefetched operands for t+1 ----
        {
            float acc = Qs[cur][ti*SP + tj] +
                        dot24((const float4*)&W[ti*SP], (const float4*)&Fs[cur][tj*SP]);
            P[ti*SP + tj] = acc;
        }
        Fs[nxt][li*SP + lj] = fN;
        Qs[nxt][li*SP + lj] = qN;
        if (tid < 96)       Hs[nxt][(tid/24)*SP + (tid%24)] = hN;
        else if (tid < 112) Rs[nxt][tid-96]  = rN;
        else if (tid < 116) ys[nxt][tid-112] = yN;
        __syncthreads();
    }
}

extern "C" void kernel_launch(void* const* d_in, const int* in_sizes, int n_in,
                              void* d_out, int out_size) {
    const float* y  = (const float*)d_in[0];
    const float* F  = (const float*)d_in[1];
    const float* Q  = (const float*)d_in[2];
    const float* H  = (const float*)d_in[3];
    const float* R  = (const float*)d_in[4];
    const float* m0 = (const float*)d_in[5];
    const float* P0 = (const float*)d_in[6];
    kalman_kernel<<<NG, NTHREADS>>>(y, F, Q, H, R, m0, P0, (float*)d_out);
}

// round 2
// speedup vs baseline: 1.3868x; 1.3868x over previous
#include <cuda_runtime.h>
#include <cuda_bf16.h>

#define NG 128
#define NT 512
#define SDIM 24
#define MDIM 4
#define SP 28          // padded row stride (floats)
#define NTH 704

__device__ __forceinline__ float dot24(const float4* __restrict__ a, const float4* __restrict__ b) {
    float acc = 0.f;
#pragma unroll
    for (int c = 0; c < 6; ++c) {
        float4 x = a[c], y = b[c];
        acc += x.x*y.x; acc += x.y*y.y; acc += x.z*y.z; acc += x.w*y.w;
    }
    return acc;
}
__device__ __forceinline__ float dot24r(const float4 fr[6], const float4* __restrict__ b) {
    float acc = 0.f;
#pragma unroll
    for (int c = 0; c < 6; ++c) {
        float4 y = b[c];
        acc += fr[c].x*y.x; acc += fr[c].y*y.y; acc += fr[c].z*y.z; acc += fr[c].w*y.w;
    }
    return acc;
}

__global__ __launch_bounds__(NTH, 1)
void kalman_kernel(const float* __restrict__ y_in,   // (G,T,M)
                   const float* __restrict__ F_in,   // (G,T,S,S)
                   const float* __restrict__ Q_in,   // (G,T,S,S)
                   const float* __restrict__ H_in,   // (G,T,M,S)
                   const float* __restrict__ R_in,   // (G,T,M,M)
                   const float* __restrict__ m0_in,  // (G,S)
                   const float* __restrict__ P0_in,  // (G,S,S)
                   float* __restrict__ out)
{
    __shared__ __align__(16) float P  [SDIM*SP];
    __shared__ __align__(16) float G1 [SDIM*SP];   // F @ P
    __shared__ __align__(16) float FPF[SDIM*SP];   // F P F^T + Q
    __shared__ __align__(16) float Fs [SDIM*SP];
    __shared__ __align__(16) float Hs [MDIM*SP];
    __shared__ __align__(16) float HP [MDIM*SP];   // H @ P
    __shared__ __align__(16) float Bm [SDIM*4];    // F P H^T
    __shared__ __align__(16) float Sinv[16];
    __shared__ __align__(16) float mvec[SDIM];
    __shared__ __align__(16) float Fm [SDIM];      // F @ m
    __shared__ float Sg[16];
    __shared__ float Hm[4];
    __shared__ float resid[4];
    __shared__ float v4[4];                        // Sinv @ resid

    const int g   = blockIdx.x;
    const int tid = threadIdx.x;
    const int w   = tid >> 5, l = tid & 31;
    const int ti  = (w % 3) * 8 + (l & 7);   // tile map, valid for tid<576
    const int tj  = (w / 3) * 4 + (l >> 3);
    const int li  = tid / 24, lj = tid % 24; // flat map for coalesced loads
    const size_t baseT = (size_t)g * NT;
    float* outMean = out;
    float* outCov  = out + (size_t)NG * NT * MDIM;

    // per-lane cofactor constants for the S-warp (warp 21, lanes 0..15)
    int ca=0, cb=0, r0=0, r1=0, r2=0, c0=0, c1=0, c2=0; float csign = 1.f;
    if (tid >= 672) {
        int sl = tid - 672;
        if (sl < 16) {
            ca = sl >> 2; cb = sl & 3;
            r0 = (ca==0)?1:0; r1 = (ca<=1)?2:1; r2 = (ca<=2)?3:2;
            c0 = (cb==0)?1:0; c1 = (cb<=1)?2:1; c2 = (cb<=2)?3:2;
            csign = ((ca+cb)&1) ? -1.f : 1.f;
        }
    }

    // register-carried per-step scalars (never hit smem)
    float qCur = 0.f, rCur = 0.f, yCur = 0.f;

    // ---- prologue: t = 0 ----
    if (tid < 576) {
        P [li*SP+lj] = P0_in[(size_t)g*576 + tid];
        Fs[li*SP+lj] = F_in[baseT*576 + tid];
        qCur = Q_in[baseT*576 + tj*24 + ti];     // Q[tj][ti] for this thread's output
        if (tid < 24) mvec[tid] = m0_in[g*24 + tid];
    } else if (tid < 672) {
        int u = tid - 576;
        Hs[(u/24)*SP + (u%24)] = H_in[baseT*96 + u];
    } else {
        int sl = tid - 672;
        if (sl < 16)       rCur = R_in[baseT*16 + sl];
        else if (sl < 20)  yCur = y_in[baseT*4 + (sl-16)];
    }
    __syncthreads();

    float4 frow[6];   // F row ti cached across stages A/B

    for (int t = 0; t < NT; ++t) {
        // ---- prefetch t+1 (consumed ~1000 cycles later in stage D) ----
        float fN=0.f, qN=0.f, hN=0.f, rN=0.f, yN=0.f;
        if (t + 1 < NT) {
            size_t b = baseT + t + 1;
            if (tid < 576) { fN = F_in[b*576 + tid]; qN = Q_in[b*576 + tj*24 + ti]; }
            else if (tid < 672) hN = H_in[b*96 + (tid-576)];
            else {
                int sl = tid - 672;
                if (sl < 16)      rN = R_in[b*16 + sl];
                else if (sl < 20) yN = y_in[b*4 + (sl-16)];
            }
        }

        // ---- Stage A: G1 = F@P, HP = H@P, Hm (-> mean out), Fm ----
        if (tid < 576) {
            const float4* fr = (const float4*)&Fs[ti*SP];
#pragma unroll
            for (int c = 0; c < 6; ++c) frow[c] = fr[c];
            G1[ti*SP+tj] = dot24r(frow, (const float4*)&P[tj*SP]);  // P symmetric
        } else if (tid < 672) {
            int u = tid-576, uq = u/24, us = u%24;
            HP[uq*SP+us] = dot24((const float4*)&Hs[uq*SP], (const float4*)&P[us*SP]);
        } else {
            int sl = tid - 672;
            if (sl < 4) {
                float hm = dot24((const float4*)&Hs[sl*SP], (const float4*)mvec);
                Hm[sl] = hm;
                outMean[(baseT+t)*4 + sl] = hm;                     // emitted mean
            } else if (sl < 28) {
                int i = sl - 4;
                Fm[i] = dot24((const float4*)&Fs[i*SP], (const float4*)mvec);
            }
        }
        __syncthreads();

        // ---- Stage B: FPF = G1@F^T + Q, B = F@(HP)^T, Sm -> Sig out + inverse ----
        if (tid < 576) {
            // FPF symmetric: this thread produces FPF[tj][ti] = G1 row tj . F row ti
            FPF[tj*SP+ti] = qCur + dot24r(frow, (const float4*)&G1[tj*SP]);
        } else if (tid < 672) {
            int u = tid-576, i = u%24, q = u/24;
            Bm[i*4+q] = dot24((const float4*)&Fs[i*SP], (const float4*)&HP[q*SP]);
        } else {
            int sl = tid - 672;
            if (sl < 16) {
                int q = sl >> 2, r = sl & 3;
                float sm = rCur + dot24((const float4*)&HP[q*SP], (const float4*)&Hs[r*SP]);
                Sg[sl] = sm;
                outCov[(baseT+t)*16 + sl] = sm;                     // emitted covariance
            } else if (sl < 20) {
                resid[sl-16] = yCur - Hm[sl-16];
            }
            __syncwarp();
            if (sl < 16) {
                // parallel 4x4 cofactor inverse (one lane per element)
                float m00=Sg[r0*4+c0], m01=Sg[r0*4+c1], m02=Sg[r0*4+c2];
                float m10=Sg[r1*4+c0], m11=Sg[r1*4+c1], m12=Sg[r1*4+c2];
                float m20=Sg[r2*4+c0], m21=Sg[r2*4+c1], m22=Sg[r2*4+c2];
                float d3 = m00*(m11*m22 - m12*m21)
                         - m01*(m10*m22 - m12*m20)
                         + m02*(m10*m21 - m11*m20);
                float cof = csign * d3;
                float contrib = (ca == 0) ? Sg[cb]*cof : 0.f;
                float det = __shfl_sync(0xffffu, contrib, 0) + __shfl_sync(0xffffu, contrib, 1)
                          + __shfl_sync(0xffffu, contrib, 2) + __shfl_sync(0xffffu, contrib, 3);
                float rdet = 1.0f / det;
                Sinv[cb*4+ca] = cof * rdet;
            }
            __syncwarp();
            if (sl < 4) {
                v4[sl] = Sinv[sl*4+0]*resid[0] + Sinv[sl*4+1]*resid[1]
                       + Sinv[sl*4+2]*resid[2] + Sinv[sl*4+3]*resid[3];
            }
        }
        if (t == NT-1) break;   // outputs for the last step are already written
        __syncthreads();

        // ---- Stage D: P = FPF - B Sinv B^T ; m = Fm + B v ; stash t+1 operands ----
        if (tid < 576) {
            float4 si0 = *(const float4*)&Sinv[0];
            float4 si1 = *(const float4*)&Sinv[4];
            float4 si2 = *(const float4*)&Sinv[8];
            float4 si3 = *(const float4*)&Sinv[12];
            float4 bi  = *(const float4*)&Bm[ti*4];
            float4 bj  = *(const float4*)&Bm[tj*4];
            float t0 = bi.x*si0.x + bi.y*si1.x + bi.z*si2.x + bi.w*si3.x;
            float t1 = bi.x*si0.y + bi.y*si1.y + bi.z*si2.y + bi.w*si3.y;
            float t2 = bi.x*si0.z + bi.y*si1.z + bi.z*si2.z + bi.w*si3.z;
            float t3 = bi.x*si0.w + bi.y*si1.w + bi.z*si2.w + bi.w*si3.w;
            float corr = t0*bj.x + t1*bj.y + t2*bj.z + t3*bj.w;
            P[ti*SP+tj] = FPF[ti*SP+tj] - corr;
            Fs[li*SP+lj] = fN;
            qCur = qN;
        } else if (tid < 672) {
            int u = tid - 576;
            Hs[(u/24)*SP + (u%24)] = hN;
        } else {
            int sl = tid - 672;
            if (sl < 24) {
                mvec[sl] = Fm[sl] + Bm[sl*4+0]*v4[0] + Bm[sl*4+1]*v4[1]
                         + Bm[sl*4+2]*v4[2] + Bm[sl*4+3]*v4[3];
            }
            if (sl < 16)      rCur = rN;
            else if (sl < 20) yCur = yN;
        }
        __syncthreads();
    }
}

extern "C" void kernel_launch(void* const* d_in, const int* in_sizes, int n_in,
                              void* d_out, int out_size) {
    const float* y  = (const float*)d_in[0];
    const float* F  = (const float*)d_in[1];
    const float* Q  = (const float*)d_in[2];
    const float* H  = (const float*)d_in[3];
    const float* R  = (const float*)d_in[4];
    const float* m0 = (const float*)d_in[5];
    const float* P0 = (const float*)d_in[6];
    kalman_kernel<<<NG, NTH>>>(y, F, Q, H, R, m0, P0, (float*)d_out);
}

// round 3
// speedup vs baseline: 1.6536x; 1.1924x over previous
#include <cuda_runtime.h>
#include <cuda_bf16.h>

#define NG 128
#define NT 512
#define SDIM 24
#define MDIM 4
#define SP 28          // padded row stride (floats)
#define NTH 704

#define BAR_T()  asm volatile("bar.sync 1, 576;" ::: "memory")
#define BAR_HS() asm volatile("bar.sync 2, 128;" ::: "memory")

// 24-dot with 4 independent FMA chains (ILP) + tree reduce.
__device__ __forceinline__ float dot24(const float4* __restrict__ a, const float4* __restrict__ b) {
    float ax = 0.f, ay = 0.f, az = 0.f, aw = 0.f;
#pragma unroll
    for (int c = 0; c < 6; ++c) {
        float4 x = a[c], y = b[c];
        ax = __fmaf_rn(x.x, y.x, ax);
        ay = __fmaf_rn(x.y, y.y, ay);
        az = __fmaf_rn(x.z, y.z, az);
        aw = __fmaf_rn(x.w, y.w, aw);
    }
    return (ax + ay) + (az + aw);
}
__device__ __forceinline__ float dot24r(const float4 fr[6], const float4* __restrict__ b) {
    float ax = 0.f, ay = 0.f, az = 0.f, aw = 0.f;
#pragma unroll
    for (int c = 0; c < 6; ++c) {
        float4 y = b[c];
        ax = __fmaf_rn(fr[c].x, y.x, ax);
        ay = __fmaf_rn(fr[c].y, y.y, ay);
        az = __fmaf_rn(fr[c].z, y.z, az);
        aw = __fmaf_rn(fr[c].w, y.w, aw);
    }
    return (ax + ay) + (az + aw);
}

__global__ __launch_bounds__(NTH, 1)
void kalman_kernel(const float* __restrict__ y_in,   // (G,T,M)
                   const float* __restrict__ F_in,   // (G,T,S,S)
                   const float* __restrict__ Q_in,   // (G,T,S,S)
                   const float* __restrict__ H_in,   // (G,T,M,S)
                   const float* __restrict__ R_in,   // (G,T,M,M)
                   const float* __restrict__ m0_in,  // (G,S)
                   const float* __restrict__ P0_in,  // (G,S,S)
                   float* __restrict__ out)
{
    __shared__ __align__(16) float P  [SDIM*SP];
    __shared__ __align__(16) float G1 [SDIM*SP];   // F @ P
    __shared__ __align__(16) float Fs [SDIM*SP];
    __shared__ __align__(16) float Hs [MDIM*SP];
    __shared__ __align__(16) float HP [MDIM*SP];   // H @ P
    __shared__ __align__(16) float Bm [SDIM*4];    // F P H^T
    __shared__ __align__(16) float Sinv[16];
    __shared__ __align__(16) float mvec[SDIM];
    __shared__ __align__(16) float Fm [SDIM];      // F @ m
    __shared__ float Sg[16];
    __shared__ float Hm[4];
    __shared__ float resid[4];
    __shared__ float v4[4];                        // Sinv @ resid

    const int g   = blockIdx.x;
    const int tid = threadIdx.x;
    const int w   = tid >> 5, l = tid & 31;
    const int ti  = (w % 3) * 8 + (l & 7);   // tile map, valid for tid<576
    const int tj  = (w / 3) * 4 + (l >> 3);
    const int li  = tid / 24, lj = tid % 24; // flat map for coalesced loads
    const size_t baseT = (size_t)g * NT;
    float* outMean = out;
    float* outCov  = out + (size_t)NG * NT * MDIM;

    // per-lane cofactor constants for the S-warp (warp 21, lanes 0..15)
    int ca=0, cb=0, r0=0, r1=0, r2=0, c0=0, c1=0, c2=0; float csign = 1.f;
    if (tid >= 672) {
        int sl = tid - 672;
        if (sl < 16) {
            ca = sl >> 2; cb = sl & 3;
            r0 = (ca==0)?1:0; r1 = (ca<=1)?2:1; r2 = (ca<=2)?3:2;
            c0 = (cb==0)?1:0; c1 = (cb<=1)?2:1; c2 = (cb<=2)?3:2;
            csign = ((ca+cb)&1) ? -1.f : 1.f;
        }
    }

    // register-carried per-step scalars
    float qCur = 0.f, rCur = 0.f, yCur = 0.f;

    // ---- prologue: t = 0 ----
    if (tid < 576) {
        P [li*SP+lj] = P0_in[(size_t)g*576 + tid];
        Fs[li*SP+lj] = F_in[baseT*576 + tid];
        qCur = Q_in[baseT*576 + tj*24 + ti];     // Q[tj][ti]
        if (tid < 24) mvec[tid] = m0_in[g*24 + tid];
    } else if (tid < 672) {
        int u = tid - 576;
        Hs[(u/24)*SP + (u%24)] = H_in[baseT*96 + u];
    } else {
        int sl = tid - 672;
        if (sl < 16)       rCur = R_in[baseT*16 + sl];
        else if (sl < 20)  yCur = y_in[baseT*4 + (sl-16)];
    }
    __syncthreads();

    float4 frow[6];        // F row ti cached across stages A/B
    float  fpfReg = 0.f;   // FPF[tj][ti] carried B -> D in a register

    for (int t = 0; t < NT; ++t) {
        // ---- prefetch t+1 (consumed in stage D) ----
        float fN=0.f, qN=0.f, hN=0.f, rN=0.f, yN=0.f;
        if (t + 1 < NT) {
            size_t b = baseT + t + 1;
            if (tid < 576)      { fN = F_in[b*576 + tid]; qN = Q_in[b*576 + tj*24 + ti]; }
            else if (tid < 672)   hN = H_in[b*96 + (tid-576)];
            else {
                int sl = tid - 672;
                if (sl < 16)      rN = R_in[b*16 + sl];
                else if (sl < 20) yN = y_in[b*4 + (sl-16)];
            }
        }

        if (tid < 576) {
            // ---- A(T): G1 = F @ P (P symmetric -> row.row) ----
            const float4* fr = (const float4*)&Fs[ti*SP];
#pragma unroll
            for (int c = 0; c < 6; ++c) frow[c] = fr[c];
            G1[ti*SP+tj] = dot24r(frow, (const float4*)&P[tj*SP]);
            BAR_T();
            // ---- B(T): FPF[tj][ti] = G1 row tj . F row ti + Q[tj][ti] (register) ----
            fpfReg = qCur + dot24r(frow, (const float4*)&G1[tj*SP]);
        } else if (tid < 672) {
            // ---- A(H): HP = H @ P ----
            int u = tid-576, uq = u/24, us = u%24;
            HP[uq*SP+us] = dot24((const float4*)&Hs[uq*SP], (const float4*)&P[us*SP]);
            BAR_HS();
            // ---- B(H): Bm = F @ HP^T ----
            int i = u%24, q = u/24;
            Bm[i*4+q] = dot24((const float4*)&Fs[i*SP], (const float4*)&HP[q*SP]);
        } else {
            // ---- A(S): Hm (-> mean out), Fm ----
            int sl = tid - 672;
            if (sl < 4) {
                float hm = dot24((const float4*)&Hs[sl*SP], (const float4*)mvec);
                Hm[sl] = hm;
                outMean[(baseT+t)*4 + sl] = hm;
            } else if (sl < 28) {
                int i = sl - 4;
                Fm[i] = dot24((const float4*)&Fs[i*SP], (const float4*)mvec);
            }
            BAR_HS();
            // ---- B(S): Sm -> Sig out, inverse, v4 ----
            if (sl < 16) {
                int q = sl >> 2, r = sl & 3;
                float sm = rCur + dot24((const float4*)&HP[q*SP], (const float4*)&Hs[r*SP]);
                Sg[sl] = sm;
                outCov[(baseT+t)*16 + sl] = sm;
            } else if (sl < 20) {
                resid[sl-16] = yCur - Hm[sl-16];
            }
            __syncwarp();
            if (sl < 16) {
                float m00=Sg[r0*4+c0], m01=Sg[r0*4+c1], m02=Sg[r0*4+c2];
                float m10=Sg[r1*4+c0], m11=Sg[r1*4+c1], m12=Sg[r1*4+c2];
                float m20=Sg[r2*4+c0], m21=Sg[r2*4+c1], m22=Sg[r2*4+c2];
                float d3 = m00*(m11*m22 - m12*m21)
                         - m01*(m10*m22 - m12*m20)
                         + m02*(m10*m21 - m11*m20);
                float cof = csign * d3;
                float contrib = (ca == 0) ? Sg[cb]*cof : 0.f;
                float det = __shfl_sync(0xffffu, contrib, 0) + __shfl_sync(0xffffu, contrib, 1)
                          + __shfl_sync(0xffffu, contrib, 2) + __shfl_sync(0xffffu, contrib, 3);
                float rdet = 1.0f / det;
                Sinv[cb*4+ca] = cof * rdet;
            }
            __syncwarp();
            if (sl < 4) {
                v4[sl] = Sinv[sl*4+0]*resid[0] + Sinv[sl*4+1]*resid[1]
                       + Sinv[sl*4+2]*resid[2] + Sinv[sl*4+3]*resid[3];
            }
        }
        if (t == NT-1) break;   // last step's outputs already written
        __syncthreads();

        // ---- D: P[tj][ti] = fpfReg - b_i Sinv b_j^T ; m = Fm + B v ; stash t+1 ----
        if (tid < 576) {
            float4 si0 = *(const float4*)&Sinv[0];
            float4 si1 = *(const float4*)&Sinv[4];
            float4 si2 = *(const float4*)&Sinv[8];
            float4 si3 = *(const float4*)&Sinv[12];
            float4 bi  = *(const float4*)&Bm[ti*4];
            float4 bj  = *(const float4*)&Bm[tj*4];
            float t0 = bi.x*si0.x + bi.y*si1.x + bi.z*si2.x + bi.w*si3.x;
            float t1 = bi.x*si0.y + bi.y*si1.y + bi.z*si2.y + bi.w*si3.y;
            float t2 = bi.x*si0.z + bi.y*si1.z + bi.z*si2.z + bi.w*si3.z;
            float t3 = bi.x*si0.w + bi.y*si1.w + bi.z*si2.w + bi.w*si3.w;
            float corr = t0*bj.x + t1*bj.y + t2*bj.z + t3*bj.w;
            P[tj*SP+ti] = fpfReg - corr;      // symmetric: write transposed slot
            Fs[li*SP+lj] = fN;
            qCur = qN;
        } else if (tid < 672) {
            int u = tid - 576;
            Hs[(u/24)*SP + (u%24)] = hN;
        } else {
            int sl = tid - 672;
            if (sl < 24) {
                mvec[sl] = Fm[sl] + Bm[sl*4+0]*v4[0] + Bm[sl*4+1]*v4[1]
                         + Bm[sl*4+2]*v4[2] + Bm[sl*4+3]*v4[3];
            }
            if (sl < 16)      rCur = rN;
            else if (sl < 20) yCur = yN;
        }
        __syncthreads();
    }
}

extern "C" void kernel_launch(void* const* d_in, const int* in_sizes, int n_in,
                              void* d_out, int out_size) {
    const float* y  = (const float*)d_in[0];
    const float* F  = (const float*)d_in[1];
    const float* Q  = (const float*)d_in[2];
    const float* H  = (const float*)d_in[3];
    const float* R  = (const float*)d_in[4];
    const float* m0 = (const float*)d_in[5];
    const float* P0 = (const float*)d_in[6];
    kalman_kernel<<<NG, NTH>>>(y, F, Q, H, R, m0, P0, (float*)d_out);
}